// round 3
// baseline (speedup 1.0000x reference)
#include <cuda_runtime.h>
#include <cuda_bf16.h>
#include <cstdint>

#define NE       64
#define ND       1024
#define NTOK     65536
#define TILE_M   128
#define KC       32              // fp32 K elements per pipeline stage
#define NCHUNK   (ND / KC)       // 32
#define NTHREADS 256

// ---- dynamic smem layout (bytes) ----
// per stage: A hi 128x32 bf16 (64B rows) 8KB | A lo 8KB | B hi 64x32 4KB | B lo 4KB
#define AH_OFF      0
#define AL_OFF      8192
#define BH_OFF      16384
#define BL_OFF      20480
#define STAGE       24576
#define BG_OFF      49152        // 64 floats bias
#define SMEM_TOTAL  49408

__device__ int g_risky_cnt;
__device__ int g_risky[NTOK];

// fp32 -> (bf16 hi, bf16 lo) pack; x -> low 16 bits (lower k index)
__device__ __forceinline__ void cvt2(float x, float y, uint32_t& h, uint32_t& l) {
    __nv_bfloat16 hx = __float2bfloat16_rn(x);
    __nv_bfloat16 hy = __float2bfloat16_rn(y);
    float rx = x - __bfloat162float(hx);
    float ry = y - __bfloat162float(hy);
    __nv_bfloat16 lx = __float2bfloat16_rn(rx);
    __nv_bfloat16 ly = __float2bfloat16_rn(ry);
    h = ((uint32_t)*reinterpret_cast<uint16_t*>(&hy) << 16) |
        *reinterpret_cast<uint16_t*>(&hx);
    l = ((uint32_t)*reinterpret_cast<uint16_t*>(&ly) << 16) |
        *reinterpret_cast<uint16_t*>(&lx);
}

// swizzled b32 load: row stride 64B (16 words), phys word = w ^ ((row&7)<<1)
__device__ __forceinline__ uint32_t ldsw(const char* base, int row, int w) {
    const int phys = w ^ ((row & 7) << 1);
    return *reinterpret_cast<const uint32_t*>(base + row * 64 + phys * 4);
}

__device__ __forceinline__ void mma16816(float c[4], const uint32_t a[4],
                                         const uint32_t b[2]) {
    asm volatile(
        "mma.sync.aligned.m16n8k16.row.col.f32.bf16.bf16.f32 "
        "{%0,%1,%2,%3}, {%4,%5,%6,%7}, {%8,%9}, {%0,%1,%2,%3};"
        : "+f"(c[0]), "+f"(c[1]), "+f"(c[2]), "+f"(c[3])
        : "r"(a[0]), "r"(a[1]), "r"(a[2]), "r"(a[3]), "r"(b[0]), "r"(b[1]));
}

// =======================================================================
__global__ __launch_bounds__(NTHREADS, 2)
void router_hmma_kernel(const float* __restrict__ tokens,
                        const int* __restrict__ t_arr,
                        const float* __restrict__ Wg,
                        const float* __restrict__ bg,
                        float* __restrict__ out)
{
    extern __shared__ char smem[];
    const int tid = threadIdx.x;
    const int wid = tid >> 5;
    const int lid = tid & 31;
    const int g   = lid >> 2;          // mma group id
    const int tg  = lid & 3;           // thread-in-group
    const int bm  = blockIdx.x * TILE_M;

    const int warp_m = (wid & 3) * 32; // warp tile 32(M) x 32(N)
    const int warp_n = (wid >> 2) * 32;

    // staging assignments
    const int am = tid >> 1, ahf = tid & 1;   // A: row, 16-float half
    const int bn = tid >> 2, bq  = tid & 3;   // B: row, 8-float quarter

    if (tid < NE) reinterpret_cast<float*>(smem + BG_OFF)[tid] = bg[tid];

    float c[2][4][4];
#pragma unroll
    for (int mt = 0; mt < 2; mt++)
#pragma unroll
        for (int nt = 0; nt < 4; nt++)
#pragma unroll
            for (int r = 0; r < 4; r++) c[mt][nt][r] = 0.0f;

    float4 la[4], lb[2];

#define LOAD(k0)                                                               \
    {                                                                          \
        const float* ga = tokens + (size_t)(bm + am) * ND + (k0) + ahf * 16;   \
        _Pragma("unroll")                                                      \
        for (int i = 0; i < 4; i++)                                            \
            la[i] = reinterpret_cast<const float4*>(ga)[i];                    \
        const float* gb = Wg + (size_t)bn * ND + (k0) + bq * 8;                \
        lb[0] = reinterpret_cast<const float4*>(gb)[0];                        \
        lb[1] = reinterpret_cast<const float4*>(gb)[1];                        \
    }

#define CVTSTORE(buf)                                                          \
    {                                                                          \
        char* st = smem + (buf) * STAGE;                                       \
        uint32_t h[8], l[8];                                                   \
        _Pragma("unroll")                                                      \
        for (int i = 0; i < 4; i++) {                                          \
            cvt2(la[i].x, la[i].y, h[2 * i], l[2 * i]);                        \
            cvt2(la[i].z, la[i].w, h[2 * i + 1], l[2 * i + 1]);                \
        }                                                                      \
        _Pragma("unroll")                                                      \
        for (int p = 0; p < 4; p++) {                                          \
            const int w0 = ahf * 8 + 2 * p;                                    \
            const int ph = w0 ^ ((am & 7) << 1);                               \
            *reinterpret_cast<uint2*>(st + AH_OFF + am * 64 + ph * 4) =        \
                make_uint2(h[2 * p], h[2 * p + 1]);                            \
            *reinterpret_cast<uint2*>(st + AL_OFF + am * 64 + ph * 4) =        \
                make_uint2(l[2 * p], l[2 * p + 1]);                            \
        }                                                                      \
        uint32_t bh[4], bl[4];                                                 \
        cvt2(lb[0].x, lb[0].y, bh[0], bl[0]);                                  \
        cvt2(lb[0].z, lb[0].w, bh[1], bl[1]);                                  \
        cvt2(lb[1].x, lb[1].y, bh[2], bl[2]);                                  \
        cvt2(lb[1].z, lb[1].w, bh[3], bl[3]);                                  \
        _Pragma("unroll")                                                      \
        for (int p = 0; p < 2; p++) {                                          \
            const int w0 = bq * 4 + 2 * p;                                     \
            const int ph = w0 ^ ((bn & 7) << 1);                               \
            *reinterpret_cast<uint2*>(st + BH_OFF + bn * 64 + ph * 4) =        \
                make_uint2(bh[2 * p], bh[2 * p + 1]);                          \
            *reinterpret_cast<uint2*>(st + BL_OFF + bn * 64 + ph * 4) =        \
                make_uint2(bl[2 * p], bl[2 * p + 1]);                          \
        }                                                                      \
    }

    LOAD(0);
    CVTSTORE(0);
    __syncthreads();

    for (int ch = 0; ch < NCHUNK; ch++) {
        const int buf = ch & 1;
        if (ch + 1 < NCHUNK) LOAD((ch + 1) * KC);

        const char* sa = smem + buf * STAGE;
#pragma unroll
        for (int s = 0; s < 2; s++) {
            const int wA0 = s * 8 + tg;
            uint32_t ah[2][4], al[2][4], bhf[4][2], blf[4][2];
#pragma unroll
            for (int mt = 0; mt < 2; mt++) {
                const int r0 = warp_m + mt * 16 + g;
                ah[mt][0] = ldsw(sa + AH_OFF, r0,     wA0);
                ah[mt][1] = ldsw(sa + AH_OFF, r0 + 8, wA0);
                ah[mt][2] = ldsw(sa + AH_OFF, r0,     wA0 + 4);
                ah[mt][3] = ldsw(sa + AH_OFF, r0 + 8, wA0 + 4);
                al[mt][0] = ldsw(sa + AL_OFF, r0,     wA0);
                al[mt][1] = ldsw(sa + AL_OFF, r0 + 8, wA0);
                al[mt][2] = ldsw(sa + AL_OFF, r0,     wA0 + 4);
                al[mt][3] = ldsw(sa + AL_OFF, r0 + 8, wA0 + 4);
            }
#pragma unroll
            for (int nt = 0; nt < 4; nt++) {
                const int n = warp_n + nt * 8 + g;
                bhf[nt][0] = ldsw(sa + BH_OFF, n, wA0);
                bhf[nt][1] = ldsw(sa + BH_OFF, n, wA0 + 4);
                blf[nt][0] = ldsw(sa + BL_OFF, n, wA0);
                blf[nt][1] = ldsw(sa + BL_OFF, n, wA0 + 4);
            }
#pragma unroll
            for (int mt = 0; mt < 2; mt++)
#pragma unroll
                for (int nt = 0; nt < 4; nt++) {
                    mma16816(c[mt][nt], ah[mt], bhf[nt]);
                    mma16816(c[mt][nt], ah[mt], blf[nt]);
                    mma16816(c[mt][nt], al[mt], bhf[nt]);
                }
        }

        if (ch + 1 < NCHUNK) CVTSTORE(buf ^ 1);   // disjoint buffer: safe pre-sync
        __syncthreads();
    }

    // ---- scatter C -> swizzled logits overlay (reuses stage smem) ----
    float* slog = reinterpret_cast<float*>(smem);   // [128][64], col e ^ (m&31)
#pragma unroll
    for (int mt = 0; mt < 2; mt++) {
        const int r0 = warp_m + mt * 16 + g;
        const int r1 = r0 + 8;
#pragma unroll
        for (int nt = 0; nt < 4; nt++) {
            const int e0 = warp_n + nt * 8 + tg * 2;
            slog[r0 * 64 + ((e0)     ^ (r0 & 31))] = c[mt][nt][0];
            slog[r0 * 64 + ((e0 + 1) ^ (r0 & 31))] = c[mt][nt][1];
            slog[r1 * 64 + ((e0)     ^ (r1 & 31))] = c[mt][nt][2];
            slog[r1 * 64 + ((e0 + 1) ^ (r1 & 31))] = c[mt][nt][3];
        }
    }
    __syncthreads();

    // ---- per-token epilogue (identical math to the 417us passing kernel) ----
    if (tid < TILE_M) {
        const int m = tid;
        const int gtok = bm + m;
        const float cap = 0.5f + 1.1f * ((float)t_arr[gtok >> 12] / 1000.0f);
        const int msw = m & 31;
        const float* row = slog + m * 64;
        const float* s_bg = reinterpret_cast<const float*>(smem + BG_OFF);

        float p[NE];
#pragma unroll
        for (int e = 0; e < NE; e++) p[e] = row[e ^ msw] + s_bg[e];

        float mx = -3.402823466e38f;
#pragma unroll 8
        for (int e = 0; e < NE; e++) mx = fmaxf(mx, p[e]);
        float s = 0.0f;
#pragma unroll 4
        for (int e = 0; e < NE; e++) { const float v = expf(p[e] - mx); s += v; p[e] = v; }
        const float inv = 1.0f / s;

        float summin = 0.0f, sumex = 0.0f;
#pragma unroll 8
        for (int e = 0; e < NE; e++) {
            const float q = 0.85f * (p[e] * inv) + (0.15f / 64.0f);
            p[e] = q;
            const float cc = fminf(q, cap);
            summin += cc;
            sumex += q - cc;
        }
        const float hs = fmaxf(64.0f * cap - summin, 1e-8f);
        const float scale = sumex / hs;

        float v1 = -1.0f, v2 = -1.0f, v3 = -1.0f;
        int i1 = 0, i2 = 0;
#pragma unroll 8
        for (int e = 0; e < NE; e++) {
            const float cc = fminf(p[e], cap);
            const float f = cc + scale * (cap - cc);
            if (f > v1)      { v3 = v2; v2 = v1; i2 = i1; v1 = f; i1 = e; }
            else if (f > v2) { v3 = v2; v2 = f; i2 = e; }
            else if (f > v3) { v3 = f; }
        }

        float* orow = out + (size_t)gtok * NE;
        const float4 z = make_float4(0.f, 0.f, 0.f, 0.f);
#pragma unroll
        for (int u = 0; u < 16; u++) reinterpret_cast<float4*>(orow)[u] = z;
        orow[i1] = v1;
        orow[i2] = v2;

        // near-tie between kept 2nd and dropped 3rd -> exact recompute pass
        if (v2 - v3 < 1e-3f) {
            const int slot = atomicAdd(&g_risky_cnt, 1);
            g_risky[slot] = gtok;
        }
    }
}

// =======================================================================
__global__ void zero_cnt_kernel() {
    if (threadIdx.x == 0 && blockIdx.x == 0) g_risky_cnt = 0;
}

// exact fp32 recompute of risky tokens (1 block = 64 threads = 1 expert each)
__global__ __launch_bounds__(64)
void fixup_kernel(const float* __restrict__ tokens,
                  const int* __restrict__ t_arr,
                  const float* __restrict__ Wg,
                  const float* __restrict__ bg,
                  float* __restrict__ out)
{
    __shared__ float sl[NE];
    const int cnt = g_risky_cnt;
    const int e = threadIdx.x;

    for (int j = blockIdx.x; j < cnt; j += gridDim.x) {
        const int m = g_risky[j];
        const float* xr = tokens + (size_t)m * ND;
        const float* wr = Wg + (size_t)e * ND;
        float acc = 0.0f;
#pragma unroll 8
        for (int k = 0; k < ND; k++) acc = fmaf(xr[k], wr[k], acc);
        sl[e] = acc + bg[e];
        __syncthreads();

        if (e == 0) {
            const float cap = 0.5f + 1.1f * ((float)t_arr[m >> 12] / 1000.0f);
            float p[NE];
            float mx = -3.402823466e38f;
            for (int q = 0; q < NE; q++) mx = fmaxf(mx, sl[q]);
            float s = 0.0f;
            for (int q = 0; q < NE; q++) { const float v = expf(sl[q] - mx); s += v; p[q] = v; }
            const float inv = 1.0f / s;
            float summin = 0.0f, sumex = 0.0f;
            for (int q = 0; q < NE; q++) {
                const float qq = 0.85f * (p[q] * inv) + (0.15f / 64.0f);
                p[q] = qq;
                const float cc = fminf(qq, cap);
                summin += cc;
                sumex += qq - cc;
            }
            const float hs = fmaxf(64.0f * cap - summin, 1e-8f);
            const float scale = sumex / hs;
            float v1 = -1.0f, v2 = -1.0f;
            int i1 = 0, i2 = 0;
            for (int q = 0; q < NE; q++) {
                const float cc = fminf(p[q], cap);
                const float f = cc + scale * (cap - cc);
                if (f > v1)      { v2 = v1; i2 = i1; v1 = f; i1 = q; }
                else if (f > v2) { v2 = f; i2 = q; }
            }
            float* orow = out + (size_t)m * NE;
            for (int u = 0; u < NE; u++) orow[u] = 0.0f;
            orow[i1] = v1;
            orow[i2] = v2;
        }
        __syncthreads();
    }
}

// =======================================================================
extern "C" void kernel_launch(void* const* d_in, const int* in_sizes, int n_in,
                              void* d_out, int out_size)
{
    const float* tokens = (const float*)d_in[0];   // (16, 4096, 1024) f32
    const int*   t_arr  = (const int*)d_in[1];     // (16,) i32
    const float* Wg     = (const float*)d_in[2];   // (64, 1024) f32
    const float* bg     = (const float*)d_in[3];   // (64,) f32
    float*       out    = (float*)d_out;           // (16, 4096, 64) f32

    cudaFuncSetAttribute(router_hmma_kernel,
                         cudaFuncAttributeMaxDynamicSharedMemorySize, SMEM_TOTAL);

    zero_cnt_kernel<<<1, 32>>>();
    router_hmma_kernel<<<NTOK / TILE_M, NTHREADS, SMEM_TOTAL>>>(
        tokens, t_arr, Wg, bg, out);
    fixup_kernel<<<1024, 64>>>(tokens, t_arr, Wg, bg, out);
}

// round 7
// speedup vs baseline: 5.8693x; 5.8693x over previous
#include <cuda_runtime.h>
#include <cstdint>

#define NE       64
#define ND       1024
#define NTOK     65536
#define TILE_M   128
#define KC       16              // fp32 K per pipeline stage
#define NCHUNK   (ND / KC)       // 64
#define NTHREADS 128

// ---- static smem layout (bytes) ----
// stages: A [2][16][128] f32 = 16KB at 0;  W [2][16][64] f32 = 8KB at 16384
// epilogue overlay: slog [128][64] f32 = 32KB at 0 (overlaps stages)
// bias: 64 f32 at 32768
#define A_OFF       0
#define A_STAGE     8192
#define W_OFF       16384
#define W_STAGE     4096
#define BG_OFF      32768
#define SMEM_BYTES  33024

// word-index XOR swizzle, depends only on k within chunk (0..15)
#define SWZ(k) ((((k) & 3) << 2) | (((k) >> 2) << 4))

__device__ __forceinline__ void fma2(unsigned long long& acc,
                                     unsigned long long a,
                                     unsigned long long b) {
    asm("fma.rn.f32x2 %0, %1, %2, %0;" : "+l"(acc) : "l"(a), "l"(b));
}
__device__ __forceinline__ unsigned long long packdup(float f) {
    unsigned long long d;
    const uint32_t u = __float_as_uint(f);
    asm("mov.b64 %0, {%1, %1};" : "=l"(d) : "r"(u));
    return d;
}

__global__ __launch_bounds__(NTHREADS, 4)
void router_ffma2_kernel(const float* __restrict__ tokens,
                         const int* __restrict__ t_arr,
                         const float* __restrict__ Wg,
                         const float* __restrict__ bg,
                         float* __restrict__ out)
{
    __shared__ __align__(16) char smem[SMEM_BYTES];
    float* sAf = reinterpret_cast<float*>(smem + A_OFF);   // [2][16][128]
    float* sWf = reinterpret_cast<float*>(smem + W_OFF);   // [2][16][64]
    float* sbg = reinterpret_cast<float*>(smem + BG_OFF);

    const int tid = threadIdx.x;
    const int bm  = blockIdx.x * TILE_M;
    const int tg  = tid & 15;          // token group: {4tg..4tg+3, 64+4tg..+3}
    const int eg  = tid >> 4;          // expert group: 8eg..8eg+7

    if (tid < NE) sbg[tid] = bg[tid];

    // acc[tp][e]: tp 0,1 = token pairs (4tg,4tg+1),(4tg+2,4tg+3);
    //             tp 2,3 = same +64.  e = expert 8eg+e.  f32x2 packed.
    unsigned long long acc[4][8];
#pragma unroll
    for (int tp = 0; tp < 4; tp++)
#pragma unroll
        for (int e = 0; e < 8; e++) acc[tp][e] = 0ull;

    float4 la[4], lw[2];

#define LOAD(k0)                                                               \
    {                                                                          \
        _Pragma("unroll")                                                      \
        for (int i = 0; i < 4; i++) {                                          \
            const int j = tid + NTHREADS * i;                                  \
            const int m = j >> 2, q = j & 3;                                   \
            la[i] = *reinterpret_cast<const float4*>(                          \
                tokens + (size_t)(bm + m) * ND + (k0) + 4 * q);                \
        }                                                                      \
        _Pragma("unroll")                                                      \
        for (int i = 0; i < 2; i++) {                                          \
            const int j = tid + NTHREADS * i;                                  \
            const int e = j >> 2, q = j & 3;                                   \
            lw[i] = *reinterpret_cast<const float4*>(                          \
                Wg + (size_t)e * ND + (k0) + 4 * q);                           \
        }                                                                      \
    }

#define STORE(buf)                                                             \
    {                                                                          \
        float* sa = sAf + (buf) * (A_STAGE / 4);                               \
        float* sw = sWf + (buf) * (W_STAGE / 4);                               \
        _Pragma("unroll")                                                      \
        for (int i = 0; i < 4; i++) {                                          \
            const int j = tid + NTHREADS * i;                                  \
            const int m = j >> 2, q = j & 3;                                   \
            const float v[4] = {la[i].x, la[i].y, la[i].z, la[i].w};           \
            _Pragma("unroll")                                                  \
            for (int r = 0; r < 4; r++) {                                      \
                const int k = 4 * q + r;                                       \
                sa[k * 128 + (m ^ SWZ(k))] = v[r];                             \
            }                                                                  \
        }                                                                      \
        _Pragma("unroll")                                                      \
        for (int i = 0; i < 2; i++) {                                          \
            const int j = tid + NTHREADS * i;                                  \
            const int e = j >> 2, q = j & 3;                                   \
            const float v[4] = {lw[i].x, lw[i].y, lw[i].z, lw[i].w};           \
            _Pragma("unroll")                                                  \
            for (int r = 0; r < 4; r++) {                                      \
                const int k = 4 * q + r;                                       \
                sw[k * 64 + (e ^ SWZ(k))] = v[r];                              \
            }                                                                  \
        }                                                                      \
    }

    LOAD(0);
    STORE(0);
    __syncthreads();

    for (int ch = 0; ch < NCHUNK; ch++) {
        const int buf = ch & 1;
        if (ch + 1 < NCHUNK) LOAD((ch + 1) * KC);

        const float* sa = sAf + buf * (A_STAGE / 4);
        const float* sw = sWf + buf * (W_STAGE / 4);

#pragma unroll
        for (int k = 0; k < KC; k++) {
            const int s = SWZ(k);
            // tokens: 2 conflict-free LDS.128 -> 4 f32x2 pairs
            const ulonglong2 A0 = *reinterpret_cast<const ulonglong2*>(
                sa + k * 128 + ((4 * tg) ^ s));
            const ulonglong2 A1 = *reinterpret_cast<const ulonglong2*>(
                sa + k * 128 + 64 + ((4 * tg) ^ s));
            // experts: 2 broadcast LDS.128 (uniform per warp half)
            // NOTE: XOR must be applied to the full expert index BEFORE any
            // arithmetic add — ((8eg)^s)+4 != (8eg+4)^s when s&4 (round-6 bug).
            const float4 w0 = *reinterpret_cast<const float4*>(
                sw + k * 64 + ((8 * eg) ^ s));
            const float4 w1 = *reinterpret_cast<const float4*>(
                sw + k * 64 + ((8 * eg + 4) ^ s));

            const unsigned long long a64[4] = {A0.x, A0.y, A1.x, A1.y};
            const unsigned long long wd[8] = {
                packdup(w0.x), packdup(w0.y), packdup(w0.z), packdup(w0.w),
                packdup(w1.x), packdup(w1.y), packdup(w1.z), packdup(w1.w)};
#pragma unroll
            for (int tp = 0; tp < 4; tp++)
#pragma unroll
                for (int e = 0; e < 8; e++) fma2(acc[tp][e], a64[tp], wd[e]);
        }

        if (ch + 1 < NCHUNK) STORE(buf ^ 1);   // disjoint buffer: safe pre-sync
        __syncthreads();
    }

    // ---- scatter acc -> swizzled logits overlay ----
    float* slog = reinterpret_cast<float*>(smem);   // [128][64], col e ^ (m&31)
#pragma unroll
    for (int tp = 0; tp < 4; tp++) {
        const int m0 = ((tp & 1) ? 4 * tg + 2 : 4 * tg) + ((tp & 2) ? 64 : 0);
        const int m1 = m0 + 1;
#pragma unroll
        for (int e = 0; e < 8; e++) {
            const int ex = 8 * eg + e;
            slog[m0 * 64 + (ex ^ (m0 & 31))] =
                __uint_as_float((uint32_t)acc[tp][e]);
            slog[m1 * 64 + (ex ^ (m1 & 31))] =
                __uint_as_float((uint32_t)(acc[tp][e] >> 32));
        }
    }
    __syncthreads();

    // ---- per-token epilogue (identical math to the 417us passing kernel) ----
    {
        const int m = tid;
        const int gtok = bm + m;
        const float cap = 0.5f + 1.1f * ((float)t_arr[gtok >> 12] / 1000.0f);
        const int msw = m & 31;
        const float* row = slog + m * 64;

        float p[NE];
#pragma unroll
        for (int e = 0; e < NE; e++) p[e] = row[e ^ msw] + sbg[e];

        float mx = -3.402823466e38f;
#pragma unroll 8
        for (int e = 0; e < NE; e++) mx = fmaxf(mx, p[e]);
        float s = 0.0f;
#pragma unroll 4
        for (int e = 0; e < NE; e++) { const float v = expf(p[e] - mx); s += v; p[e] = v; }
        const float inv = 1.0f / s;

        float summin = 0.0f, sumex = 0.0f;
#pragma unroll 8
        for (int e = 0; e < NE; e++) {
            const float q = 0.85f * (p[e] * inv) + (0.15f / 64.0f);
            p[e] = q;
            const float cc = fminf(q, cap);
            summin += cc;
            sumex += q - cc;
        }
        const float hs = fmaxf(64.0f * cap - summin, 1e-8f);
        const float scale = sumex / hs;

        float v1 = -1.0f, v2 = -1.0f;
        int i1 = 0, i2 = 0;
#pragma unroll 8
        for (int e = 0; e < NE; e++) {
            const float cc = fminf(p[e], cap);
            const float f = cc + scale * (cap - cc);
            if (f > v1)      { v2 = v1; i2 = i1; v1 = f; i1 = e; }
            else if (f > v2) { v2 = f; i2 = e; }
        }

        float* orow = out + (size_t)gtok * NE;
        const float4 z = make_float4(0.f, 0.f, 0.f, 0.f);
#pragma unroll
        for (int u = 0; u < 16; u++) reinterpret_cast<float4*>(orow)[u] = z;
        orow[i1] = v1;
        orow[i2] = v2;
    }
}

extern "C" void kernel_launch(void* const* d_in, const int* in_sizes, int n_in,
                              void* d_out, int out_size)
{
    const float* tokens = (const float*)d_in[0];   // (16, 4096, 1024) f32
    const int*   t_arr  = (const int*)d_in[1];     // (16,) i32
    const float* Wg     = (const float*)d_in[2];   // (64, 1024) f32
    const float* bg     = (const float*)d_in[3];   // (64,) f32
    float*       out    = (float*)d_out;           // (16, 4096, 64) f32

    router_ffma2_kernel<<<NTOK / TILE_M, NTHREADS>>>(tokens, t_arr, Wg, bg, out);
}